// round 4
// baseline (speedup 1.0000x reference)
#include <cuda_runtime.h>
#include <cuda_fp16.h>
#include <cstdint>

// Inputs (metadata order):
// 0: x [N,64] f32   1: node_batch [N] int32-or-int64 (sorted)  2: global_attr [B,3] f32
// 3: Wg [3,64] f32  4: bg [64] f32  5: Wn [128,64] f32  6: bn [64] f32
// 7: Wa [64,1] f32  8: ba [1] f32
// out: w [N,1] f32   (used as scratch for s, then e, then w)

#define BMAX 8192
#define BMSK (BMAX - 1)

__device__ float    d_c[BMAX * 64];   // c[b] = (ga_b@Wg+bg) @ Wn[64:] + bn
__device__ unsigned d_gmax[BMAX];
__device__ float    d_gsum[BMAX];
__device__ int      d_is64;

// ---------------- helpers ----------------

__device__ __forceinline__ uint32_t s2u(const void* p) {
    return (uint32_t)__cvta_generic_to_shared(p);
}

__device__ __forceinline__ void ldm_x4(uint32_t* r, uint32_t addr) {
    asm volatile("ldmatrix.sync.aligned.m8n8.x4.shared.b16 {%0,%1,%2,%3}, [%4];"
                 : "=r"(r[0]), "=r"(r[1]), "=r"(r[2]), "=r"(r[3]) : "r"(addr));
}
__device__ __forceinline__ void ldm_x4t(uint32_t* r, uint32_t addr) {
    asm volatile("ldmatrix.sync.aligned.m8n8.x4.trans.shared.b16 {%0,%1,%2,%3}, [%4];"
                 : "=r"(r[0]), "=r"(r[1]), "=r"(r[2]), "=r"(r[3]) : "r"(addr));
}
__device__ __forceinline__ void mma16816(float* d, const uint32_t* a, const uint32_t* b) {
    asm volatile("mma.sync.aligned.m16n8k16.row.col.f32.f16.f16.f32 "
                 "{%0,%1,%2,%3}, {%4,%5,%6,%7}, {%8,%9}, {%0,%1,%2,%3};"
                 : "+f"(d[0]), "+f"(d[1]), "+f"(d[2]), "+f"(d[3])
                 : "r"(a[0]), "r"(a[1]), "r"(a[2]), "r"(a[3]), "r"(b[0]), "r"(b[1]));
}

__device__ __forceinline__ unsigned enc_f(float f) {
    unsigned u = __float_as_uint(f);
    return (u & 0x80000000u) ? ~u : (u | 0x80000000u);
}
__device__ __forceinline__ float dec_f(unsigned u) {
    return __uint_as_float((u & 0x80000000u) ? (u & 0x7FFFFFFFu) : ~u);
}

// segment id read, dtype-branched; always in-bounds under either dtype
__device__ __forceinline__ int seg_at(const void* nbraw, int i) {
    if (d_is64) return ((int)((const long long*)nbraw)[i]) & BMSK;
    return ((const int*)nbraw)[i] & BMSK;
}

// stable softplus via EX2/LG2
__device__ __forceinline__ float softplusf(float z) {
    float az = fabsf(z);
    float t = az * -1.4426950408889634f;
    float p, l;
    asm("ex2.approx.ftz.f32 %0, %1;" : "=f"(p) : "f"(t));
    float op = 1.0f + p;
    asm("lg2.approx.ftz.f32 %0, %1;" : "=f"(l) : "f"(op));
    return fmaxf(z, 0.0f) + 0.6931471805599453f * l;
}

// ---------------- kernel 0: detect node_batch dtype ----------------
// Reads only word indices < n: safe under int32 (4n B) and int64 (8n B).
// int64: odd word indices are high words of sorted nonneg values -> 0.
// int32: values near the end are the largest segment ids -> nonzero.
__global__ void k_detect(const int* __restrict__ p32, int n) {
    int last = n - 1;
    if (!(last & 1)) last--;           // make it odd
    int acc = 0;
    for (int k = 0; k < 8; k++) {
        int idx = last - 2 * k;
        if (idx >= 1) acc |= p32[idx];
    }
    d_is64 = (acc == 0) ? 1 : 0;
}

// ---------------- kernel 1: per-graph c[b] + init reductions ----------------

__global__ void k_graph(const float* __restrict__ ga, const float* __restrict__ Wg,
                        const float* __restrict__ bg, const float* __restrict__ Wn,
                        const float* __restrict__ bn) {
    int b = blockIdx.x;
    int j = threadIdx.x; // 0..63
    __shared__ float g[64];
    float a0 = ga[b * 3 + 0], a1 = ga[b * 3 + 1], a2 = ga[b * 3 + 2];
    g[j] = bg[j] + a0 * Wg[j] + a1 * Wg[64 + j] + a2 * Wg[128 + j];
    if (j == 0) {
        d_gmax[b] = enc_f(__int_as_float(0xFF800000));
        d_gsum[b] = 0.0f;
    }
    __syncthreads();
    float acc = bn[j];
#pragma unroll
    for (int i = 0; i < 64; i++)
        acc = fmaf(g[i], Wn[(64 + i) * 64 + j], acc);
    d_c[b * 64 + j] = acc;
}

// ---------------- kernel 2: fused GEMM + softplus + dot + segment max ----------------

#define LDA 72
#define LDB 72

__global__ void __launch_bounds__(128)
k_main(const float* __restrict__ x, const void* __restrict__ nbraw,
       const float* __restrict__ Wn, const float* __restrict__ Wa,
       const float* __restrict__ ba, float* __restrict__ out, int n) {
    __shared__ __align__(16) __half smA[128 * LDA];
    __shared__ __align__(16) __half smB[64 * LDB];
    __shared__ float sWa[64];
    __shared__ float sba;

    const int tid = threadIdx.x;
    const int wid = tid >> 5;
    const int lane = tid & 31;
    const int wbase = wid * 32;
    const int r0 = blockIdx.x * 128;

    if (tid == 0) sba = ba[0];
    if (tid < 64) sWa[tid] = Wa[tid];

    // B = Wn[0:64,:] row-major (k x n), f32 -> f16
#pragma unroll
    for (int it = 0; it < 16; it++) {
        int idx = it * 256 + tid * 2;
        int k = idx >> 6;
        int nn = idx & 63;
        float2 w = *reinterpret_cast<const float2*>(Wn + k * 64 + nn);
        __half2 h = __floats2half2_rn(w.x, w.y);
        *reinterpret_cast<__half2*>(smB + k * LDB + nn) = h;
    }

    // A = x tile [128,64] f32 -> f16 (zero-pad tail rows)
#pragma unroll
    for (int it = 0; it < 16; it++) {
        int f4 = it * 128 + tid;
        int row = f4 >> 4;
        int c4 = (f4 & 15) * 4;
        int g = r0 + row;
        float4 v = make_float4(0.f, 0.f, 0.f, 0.f);
        if (g < n) v = *reinterpret_cast<const float4*>(x + (long long)g * 64 + c4);
        __half2 h0 = __floats2half2_rn(v.x, v.y);
        __half2 h1 = __floats2half2_rn(v.z, v.w);
        uint2 pv;
        pv.x = *reinterpret_cast<uint32_t*>(&h0);
        pv.y = *reinterpret_cast<uint32_t*>(&h1);
        *reinterpret_cast<uint2*>(smA + row * LDA + c4) = pv;
    }
    __syncthreads();

    const uint32_t aA = s2u(smA), aB = s2u(smB);

    // MMA: warp computes rows [wbase, wbase+32) x cols [0,64), K=64
    float d[2][8][4];
#pragma unroll
    for (int mt = 0; mt < 2; mt++)
#pragma unroll
        for (int nt = 0; nt < 8; nt++)
#pragma unroll
            for (int q = 0; q < 4; q++) d[mt][nt][q] = 0.f;

#pragma unroll
    for (int kk = 0; kk < 4; kk++) {
        uint32_t a[2][4];
#pragma unroll
        for (int mt = 0; mt < 2; mt++) {
            uint32_t addr = aA + ((wbase + mt * 16 + (lane & 15)) * LDA +
                                  kk * 16 + ((lane >> 4) << 3)) * 2;
            ldm_x4(a[mt], addr);
        }
        uint32_t b[16];
#pragma unroll
        for (int np = 0; np < 4; np++) {
            uint32_t addr = aB + ((kk * 16 + (lane & 15)) * LDB +
                                  np * 16 + ((lane >> 4) << 3)) * 2;
            ldm_x4t(b + np * 4, addr);
        }
#pragma unroll
        for (int mt = 0; mt < 2; mt++)
#pragma unroll
            for (int nt = 0; nt < 8; nt++)
                mma16816(d[mt][nt], a[mt], b + nt * 2);
    }

    // Epilogue in registers.
    const int g8 = lane >> 2;
    const int l3 = lane & 3;

    float2 wv[8];
#pragma unroll
    for (int nt = 0; nt < 8; nt++)
        wv[nt] = *reinterpret_cast<const float2*>(sWa + nt * 8 + 2 * l3);

    float sum[4]; // slot = mt*2 + h
#pragma unroll
    for (int mt = 0; mt < 2; mt++) {
#pragma unroll
        for (int h = 0; h < 2; h++) {
            int row = wbase + mt * 16 + h * 8 + g8;
            int gr = r0 + row;
            int sg = (gr < n) ? seg_at(nbraw, gr) : 0;
            const float2* cp = reinterpret_cast<const float2*>(d_c + sg * 64);
            float acc = 0.f;
#pragma unroll
            for (int nt = 0; nt < 8; nt++) {
                float2 cc = __ldg(cp + nt * 4 + l3);
                float v0 = d[mt][nt][h * 2 + 0] + cc.x;
                float v1 = d[mt][nt][h * 2 + 1] + cc.y;
                acc = fmaf(wv[nt].x, softplusf(v0), acc);
                acc = fmaf(wv[nt].y, softplusf(v1), acc);
            }
            acc += __shfl_xor_sync(0xFFFFFFFFu, acc, 1);
            acc += __shfl_xor_sync(0xFFFFFFFFu, acc, 2);
            sum[mt * 2 + h] = acc + sba;
        }
    }

    // Permute so lane L holds row wbase+L (coalesced store + contiguous seg scan).
    int slot = ((lane >> 4) & 1) * 2 + ((lane >> 3) & 1);
    int owner = (lane & 7) * 4 + slot;
    float v0 = __shfl_sync(0xFFFFFFFFu, sum[0], owner);
    float v1 = __shfl_sync(0xFFFFFFFFu, sum[1], owner);
    float v2 = __shfl_sync(0xFFFFFFFFu, sum[2], owner);
    float v3 = __shfl_sync(0xFFFFFFFFu, sum[3], owner);
    float myval = (slot == 0) ? v0 : (slot == 1) ? v1 : (slot == 2) ? v2 : v3;

    int gidx = r0 + wbase + lane;
    bool act = (gidx < n);
    int sg = act ? seg_at(nbraw, gidx) : -1;
    if (act) out[gidx] = myval;   // stash score s in out

    // Warp-segmented max over contiguous sorted segments
    float v = act ? myval : __int_as_float(0xFF800000);
#pragma unroll
    for (int off = 1; off < 32; off <<= 1) {
        float ov = __shfl_down_sync(0xFFFFFFFFu, v, off);
        int og = __shfl_down_sync(0xFFFFFFFFu, sg, off);
        if (lane + off < 32 && og == sg) v = fmaxf(v, ov);
    }
    int prev = __shfl_up_sync(0xFFFFFFFFu, sg, 1);
    if ((lane == 0 || prev != sg) && sg >= 0)
        atomicMax(&d_gmax[sg], enc_f(v));
}

// ---------------- kernel 3: e = exp(s - m[seg]), segmented sum ----------------

__global__ void k_exp(const void* __restrict__ nbraw, float* __restrict__ out, int n) {
    int i = blockIdx.x * blockDim.x + threadIdx.x;
    int lane = threadIdx.x & 31;
    int sg = -1;
    float e = 0.0f;
    if (i < n) {
        sg = seg_at(nbraw, i);
        float m = dec_f(d_gmax[sg]);
        float t = (out[i] - m) * 1.4426950408889634f;
        asm("ex2.approx.ftz.f32 %0, %1;" : "=f"(e) : "f"(t));
        out[i] = e;
    }
    float v = e;
#pragma unroll
    for (int off = 1; off < 32; off <<= 1) {
        float ov = __shfl_down_sync(0xFFFFFFFFu, v, off);
        int og = __shfl_down_sync(0xFFFFFFFFu, sg, off);
        if (lane + off < 32 && og == sg) v += ov;
    }
    int prev = __shfl_up_sync(0xFFFFFFFFu, sg, 1);
    if ((lane == 0 || prev != sg) && sg >= 0)
        atomicAdd(&d_gsum[sg], v);
}

// ---------------- kernel 4: normalize ----------------

__global__ void k_norm(const void* __restrict__ nbraw, float* __restrict__ out, int n) {
    int i = blockIdx.x * blockDim.x + threadIdx.x;
    if (i < n) {
        int sg = seg_at(nbraw, i);
        out[i] = out[i] / (d_gsum[sg] + 1e-16f);
    }
}

// ---------------- launch ----------------

extern "C" void kernel_launch(void* const* d_in, const int* in_sizes, int n_in,
                              void* d_out, int out_size) {
    const float* x = (const float*)d_in[0];
    const void* nb = d_in[1];
    const float* ga = (const float*)d_in[2];
    const float* Wg = (const float*)d_in[3];
    const float* bg = (const float*)d_in[4];
    const float* Wn = (const float*)d_in[5];
    const float* bn = (const float*)d_in[6];
    const float* Wa = (const float*)d_in[7];
    const float* ba = (const float*)d_in[8];
    float* out = (float*)d_out;

    int n = in_sizes[0] / 64;
    if (n > out_size) n = out_size;   // never index out beyond its size
    int B = in_sizes[2] / 3;
    if (B > BMAX) B = BMAX;

    int blk = (n + 255) / 256;

    k_detect<<<1, 1>>>((const int*)nb, n);
    k_graph<<<B, 64>>>(ga, Wg, bg, Wn, bn);

    int tiles = (n + 127) / 128;
    k_main<<<tiles, 128>>>(x, nb, Wn, Wa, ba, out, n);

    k_exp<<<blk, 256>>>(nb, out, n);
    k_norm<<<blk, 256>>>(nb, out, n);
}